// round 1
// baseline (speedup 1.0000x reference)
#include <cuda_runtime.h>
#include <cstdint>
#include <cstddef>

#define N_NODES 50000
#define N_EDGES 800000
#define DIN     128
#define HC      128
#define ED      32

// ---------------- scratch (device globals; no allocations allowed) ----------
__device__ __align__(16) float g_Q[N_NODES * HC];
__device__ __align__(16) float g_K[N_NODES * HC];
__device__ __align__(16) float g_V[N_NODES * HC];
__device__ __align__(16) float g_QW[N_NODES * 64];      // [N][H=2][32] = q @ We_h^T
__device__ __align__(16) float g_Wqe[DIN * 64];         // combined Wq@We_h^T  [128][64]
__device__ __align__(16) float g_bqW[64];
__device__ __align__(16) float g_alpha[N_EDGES * 2];    // exp(logit)
__device__ __align__(16) float g_denom[N_NODES * 2];    // then inverted in-place
__device__ __align__(16) float g_aggEA[N_NODES * 64];   // [N][H=2][32] sum alpha*edge_attr

// ---------------- f32x2 helpers (Blackwell packed fp32) ---------------------
typedef unsigned long long u64;
__device__ __forceinline__ u64 pack2(float a, float b) {
    u64 r; asm("mov.b64 %0, {%1, %2};" : "=l"(r) : "f"(a), "f"(b)); return r;
}
__device__ __forceinline__ void unpack2(u64 v, float& a, float& b) {
    asm("mov.b64 {%0, %1}, %2;" : "=f"(a), "=f"(b) : "l"(v));
}
__device__ __forceinline__ u64 fma2(u64 a, u64 b, u64 c) {
    u64 d; asm("fma.rn.f32x2 %0, %1, %2, %3;" : "=l"(d) : "l"(a), "l"(b), "l"(c)); return d;
}

// ---------------- zero scratch ----------------------------------------------
__global__ void zero_scratch() {
    int i = blockIdx.x * 256 + threadIdx.x;          // grid covers 3,200,000
    if (i < N_NODES * 2) g_denom[i] = 0.0f;
    if (i < N_NODES * 64) g_aggEA[i] = 0.0f;
}

// ---------------- combined weight Wqe = fold(We into Wq), bias too ----------
__global__ void combine_we(const float* __restrict__ Wq, const float* __restrict__ bq,
                           const float* __restrict__ We) {
    int g = blockIdx.x * 256 + threadIdx.x;
    if (g < DIN * 64) {
        int r = g >> 6, o = g & 63;
        int h = o >> 5, d = o & 31, base = h * 64;
        float s = 0.0f;
        for (int c = 0; c < 64; c++)
            s += Wq[r * HC + base + c] * We[d * HC + base + c];
        g_Wqe[r * 64 + o] = s;
    } else if (g < DIN * 64 + 64) {
        int o = g - DIN * 64;
        int h = o >> 5, d = o & 31, base = h * 64;
        float s = 0.0f;
        for (int c = 0; c < 64; c++)
            s += bq[base + c] * We[d * HC + base + c];
        g_bqW[o] = s;
    }
}

// ---------------- node GEMM: D[M,ncols] = A[M,128] @ B[128,ncols] + bias ----
// which: 0->g_Q 1->g_K 2->g_V 3->Dext(d_out, skip) 4->g_QW (B=g_Wqe, bias=g_bqW)
__global__ __launch_bounds__(256, 2)
void gemm128(const float* __restrict__ A, const float* __restrict__ B,
             const float* __restrict__ bias, float* __restrict__ Dext,
             int which, int ncols, int M) {
    __shared__ float As[32][132];   // [k][m], padded
    __shared__ float Bs[32][128];   // [k][n]

    const float* Bp = (which == 4) ? g_Wqe : B;
    const float* bp = (which == 4) ? g_bqW : bias;
    float* D;
    switch (which) {
        case 0: D = g_Q;  break;
        case 1: D = g_K;  break;
        case 2: D = g_V;  break;
        case 4: D = g_QW; break;
        default: D = Dext; break;
    }

    int m0 = blockIdx.x * 128;
    int t  = threadIdx.x;
    int tx = t & 15, ty = t >> 4;
    int ldb4 = ncols >> 2;

    u64 acc[8][4];
#pragma unroll
    for (int r = 0; r < 8; r++)
#pragma unroll
        for (int p = 0; p < 4; p++) acc[r][p] = 0ULL;

    for (int kk = 0; kk < 4; kk++) {
        // A tile: rows m0..m0+127, k in [kk*32, kk*32+32)
#pragma unroll
        for (int i = 0; i < 4; i++) {
            int row = (t >> 3) + i * 32;
            int c4  = t & 7;
            float4 v = make_float4(0.f, 0.f, 0.f, 0.f);
            if (m0 + row < M)
                v = ((const float4*)A)[(size_t)(m0 + row) * 32 + kk * 8 + c4];
            As[c4 * 4 + 0][row] = v.x;
            As[c4 * 4 + 1][row] = v.y;
            As[c4 * 4 + 2][row] = v.z;
            As[c4 * 4 + 3][row] = v.w;
        }
        // B tile: k rows [kk*32, +32), all ncols (zero-pad to 128)
#pragma unroll
        for (int i = 0; i < 4; i++) {
            int idx = i * 256 + t;        // 0..1023 float4 slots
            int r   = idx >> 5;           // 0..31
            int c4  = idx & 31;           // 0..31
            float4 v = make_float4(0.f, 0.f, 0.f, 0.f);
            if (c4 * 4 < ncols)
                v = ((const float4*)Bp)[(size_t)(kk * 32 + r) * ldb4 + c4];
            ((float4*)&Bs[r][0])[c4] = v;
        }
        __syncthreads();
#pragma unroll
        for (int k = 0; k < 32; k++) {
            float4 a0 = ((const float4*)&As[k][0])[ty];
            float4 a1 = ((const float4*)&As[k][0])[16 + ty];
            float4 b0 = ((const float4*)&Bs[k][0])[tx];
            float4 b1 = ((const float4*)&Bs[k][0])[16 + tx];
            u64 bpk[4] = { pack2(b0.x, b0.y), pack2(b0.z, b0.w),
                           pack2(b1.x, b1.y), pack2(b1.z, b1.w) };
            float av[8] = { a0.x, a0.y, a0.z, a0.w, a1.x, a1.y, a1.z, a1.w };
#pragma unroll
            for (int r = 0; r < 8; r++) {
                u64 ad = pack2(av[r], av[r]);
#pragma unroll
                for (int p = 0; p < 4; p++)
                    acc[r][p] = fma2(ad, bpk[p], acc[r][p]);
            }
        }
        __syncthreads();
    }

#pragma unroll
    for (int r = 0; r < 8; r++) {
        int mrow = (r < 4) ? (ty * 4 + r) : (64 + ty * 4 + r - 4);
        int m = m0 + mrow;
        if (m >= M) continue;
#pragma unroll
        for (int p = 0; p < 4; p++) {
            int c = (p < 2) ? (tx * 4 + p * 2) : (64 + tx * 4 + (p - 2) * 2);
            if (c >= ncols) continue;
            float lo, hi;
            unpack2(acc[r][p], lo, hi);
            float2 st = make_float2(lo + bp[c], hi + bp[c + 1]);
            *(float2*)&D[(size_t)m * ncols + c] = st;
        }
    }
}

// ---------------- pass 1: logits -> exp, segment-sum denom ------------------
__global__ __launch_bounds__(256)
void edge_alpha(const int* __restrict__ ei, const float* __restrict__ ea) {
    int e    = blockIdx.x * 8 + (threadIdx.x >> 5);
    int lane = threadIdx.x & 31;
    int src = ei[e];
    int dst = ei[N_EDGES + e];

    float4 q = ((const float4*)g_Q)[(size_t)dst * 32 + lane];
    float4 k = ((const float4*)g_K)[(size_t)src * 32 + lane];
    float qk = q.x * k.x + q.y * k.y + q.z * k.z + q.w * k.w;
#pragma unroll
    for (int s = 8; s >= 1; s >>= 1) qk += __shfl_xor_sync(0xffffffffu, qk, s);

    float qe = 0.0f;
    if (lane < 16) {
        float4 t = ((const float4*)ea)[(size_t)e * 8 + (lane & 7)];
        float4 w = ((const float4*)g_QW)[(size_t)dst * 16 + lane];
        qe = t.x * w.x + t.y * w.y + t.z * w.z + t.w * w.w;
    }
#pragma unroll
    for (int s = 4; s >= 1; s >>= 1) qe += __shfl_xor_sync(0xffffffffu, qe, s);

    float qk0 = __shfl_sync(0xffffffffu, qk, 0);
    float qk1 = __shfl_sync(0xffffffffu, qk, 16);
    float qe0 = __shfl_sync(0xffffffffu, qe, 0);
    float qe1 = __shfl_sync(0xffffffffu, qe, 8);

    if (lane < 2) {
        float logit = ((lane ? qk1 : qk0) + (lane ? qe1 : qe0)) * 0.125f;
        float a = expf(logit);   // softmax shift-invariant; logits are O(1), no max needed
        g_alpha[2 * (size_t)e + lane] = a;
        atomicAdd(&g_denom[2 * dst + lane], a);
    }
}

// ---------------- invert denominators ---------------------------------------
__global__ void inv_denom() {
    int i = blockIdx.x * 256 + threadIdx.x;
    if (i < N_NODES * 2) g_denom[i] = 1.0f / (g_denom[i] + 1e-16f);
}

// ---------------- pass 2: weighted aggregation (vector reds) ----------------
__global__ __launch_bounds__(256)
void edge_agg(const int* __restrict__ ei, const float* __restrict__ ea,
              float* __restrict__ out) {
    int e    = blockIdx.x * 8 + (threadIdx.x >> 5);
    int lane = threadIdx.x & 31;
    int src = ei[e];
    int dst = ei[N_EDGES + e];

    float w0 = g_alpha[2 * (size_t)e]     * g_denom[2 * dst];
    float w1 = g_alpha[2 * (size_t)e + 1] * g_denom[2 * dst + 1];

    float4 v = ((const float4*)g_V)[(size_t)src * 32 + lane];
    float w  = (lane < 16) ? w0 : w1;
    float* p = out + (size_t)dst * HC + lane * 4;
    asm volatile("red.global.add.v4.f32 [%0], {%1, %2, %3, %4};"
                 :: "l"(p), "f"(v.x * w), "f"(v.y * w), "f"(v.z * w), "f"(v.w * w)
                 : "memory");

    if (lane < 16) {
        float4 t  = ((const float4*)ea)[(size_t)e * 8 + (lane & 7)];
        float we  = (lane < 8) ? w0 : w1;
        float* pe = g_aggEA + (size_t)dst * 64 + lane * 4;
        asm volatile("red.global.add.v4.f32 [%0], {%1, %2, %3, %4};"
                     :: "l"(pe), "f"(t.x * we), "f"(t.y * we), "f"(t.z * we), "f"(t.w * we)
                     : "memory");
    }
}

// ---------------- finalize: out += aggEA @ We (per head) --------------------
__global__ __launch_bounds__(256)
void finalize(const float* __restrict__ We, float* __restrict__ out) {
    __shared__ float We_s[32][128];
    __shared__ float agg_s[16][64];
    int t  = threadIdx.x;
    int n0 = blockIdx.x * 16;

#pragma unroll
    for (int i = 0; i < 4; i++) {
        int idx = i * 256 + t;            // 1024 float4
        int d   = idx >> 5;
        int c4  = idx & 31;
        ((float4*)&We_s[d][0])[c4] = ((const float4*)We)[idx];
    }
    {
        int n_l = t >> 4, c4 = t & 15;
        ((float4*)&agg_s[n_l][0])[c4] =
            ((const float4*)g_aggEA)[(size_t)(n0 + n_l) * 16 + c4];
    }
    __syncthreads();

    int n_l = t >> 4;
    int cb  = (t & 15) * 8;
    int h   = cb >> 6;                    // fixed per thread (8-col group within one head)
    float a[32];
#pragma unroll
    for (int d = 0; d < 32; d++) a[d] = agg_s[n_l][h * 32 + d];

    int n = n0 + n_l;
#pragma unroll
    for (int j = 0; j < 8; j++) {
        int c = cb + j;
        float s = 0.0f;
#pragma unroll
        for (int d = 0; d < 32; d++) s += a[d] * We_s[d][c];
        out[(size_t)n * HC + c] += s;
    }
}

// ---------------- launcher ---------------------------------------------------
extern "C" void kernel_launch(void* const* d_in, const int* in_sizes, int n_in,
                              void* d_out, int out_size) {
    const float* x  = (const float*)d_in[0];
    const int*   ei = (const int*)d_in[1];
    const float* ea = (const float*)d_in[2];
    const float* Wq = (const float*)d_in[3];
    const float* bq = (const float*)d_in[4];
    const float* Wk = (const float*)d_in[5];
    const float* bk = (const float*)d_in[6];
    const float* Wv = (const float*)d_in[7];
    const float* bv = (const float*)d_in[8];
    const float* We = (const float*)d_in[9];
    const float* Ws = (const float*)d_in[10];
    const float* bs = (const float*)d_in[11];
    float* out = (float*)d_out;

    zero_scratch<<<12500, 256>>>();
    combine_we<<<33, 256>>>(Wq, bq, We);

    const int gm = (N_NODES + 127) / 128;   // 391
    gemm128<<<gm, 256>>>(x, Wq, bq, nullptr, 0, 128, N_NODES);   // Q
    gemm128<<<gm, 256>>>(x, Wk, bk, nullptr, 1, 128, N_NODES);   // K
    gemm128<<<gm, 256>>>(x, Wv, bv, nullptr, 2, 128, N_NODES);   // V
    gemm128<<<gm, 256>>>(x, Ws, bs, out,     3, 128, N_NODES);   // skip -> d_out
    gemm128<<<gm, 256>>>(x, nullptr, nullptr, nullptr, 4, 64, N_NODES); // qW

    edge_alpha<<<N_EDGES / 8, 256>>>(ei, ea);
    inv_denom<<<391, 256>>>();
    edge_agg<<<N_EDGES / 8, 256>>>(ei, ea, out);
    finalize<<<N_NODES / 16, 256>>>(We, out);
}

// round 2
// speedup vs baseline: 1.6572x; 1.6572x over previous
#include <cuda_runtime.h>
#include <cstdint>
#include <cstddef>

#define N_NODES 50000
#define N_EDGES 800000
#define DIN     128
#define HC      128
#define ED      32

// ---------------- scratch (device globals; no allocations allowed) ----------
__device__ __align__(16) float g_Q[N_NODES * HC];
__device__ __align__(16) float g_K[N_NODES * HC];
__device__ __align__(16) float g_V[N_NODES * HC];
__device__ __align__(16) float g_QW[N_NODES * 64];      // [N][H=2][32] = q @ We_h^T
__device__ __align__(16) float g_Wqe[DIN * 64];         // combined Wq@We_h^T  [128][64]
__device__ __align__(16) float g_bqW[64];

// sort scratch
__device__ int  g_hist[N_NODES];
__device__ int  g_off[N_NODES];
__device__ int  g_cursor[N_NODES];
__device__ int  g_bsum[256];
__device__ int  g_bpre[256];
__device__ __align__(8) int2 g_sorted2[N_EDGES];        // (src, edge_id) sorted by dst

// ---------------- f32x2 helpers (Blackwell packed fp32) ---------------------
typedef unsigned long long u64;
__device__ __forceinline__ u64 pack2(float a, float b) {
    u64 r; asm("mov.b64 %0, {%1, %2};" : "=l"(r) : "f"(a), "f"(b)); return r;
}
__device__ __forceinline__ void unpack2(u64 v, float& a, float& b) {
    asm("mov.b64 {%0, %1}, %2;" : "=f"(a), "=f"(b) : "l"(v));
}
__device__ __forceinline__ u64 fma2(u64 a, u64 b, u64 c) {
    u64 d; asm("fma.rn.f32x2 %0, %1, %2, %3;" : "=l"(d) : "l"(a), "l"(b), "l"(c)); return d;
}

// ---------------- zero hist --------------------------------------------------
__global__ void zero_hist() {
    int i = blockIdx.x * 256 + threadIdx.x;
    if (i < N_NODES) g_hist[i] = 0;
}

// ---------------- combined weight Wqe = fold(We into Wq), bias too ----------
__global__ void combine_we(const float* __restrict__ Wq, const float* __restrict__ bq,
                           const float* __restrict__ We) {
    int g = blockIdx.x * 256 + threadIdx.x;
    if (g < DIN * 64) {
        int r = g >> 6, o = g & 63;
        int h = o >> 5, d = o & 31, base = h * 64;
        float s = 0.0f;
        for (int c = 0; c < 64; c++)
            s += Wq[r * HC + base + c] * We[d * HC + base + c];
        g_Wqe[r * 64 + o] = s;
    } else if (g < DIN * 64 + 64) {
        int o = g - DIN * 64;
        int h = o >> 5, d = o & 31, base = h * 64;
        float s = 0.0f;
        for (int c = 0; c < 64; c++)
            s += bq[base + c] * We[d * HC + base + c];
        g_bqW[o] = s;
    }
}

// ---------------- node GEMM, batched over blockIdx.y = which ----------------
// y: 0->g_Q 1->g_K 2->g_V 3->out(skip) 4->g_QW (B=g_Wqe, bias=g_bqW, ncols=64)
__global__ __launch_bounds__(256, 2)
void gemm128(const float* __restrict__ A,
             const float* __restrict__ Wq, const float* __restrict__ bq,
             const float* __restrict__ Wk, const float* __restrict__ bk,
             const float* __restrict__ Wv, const float* __restrict__ bv,
             const float* __restrict__ Ws, const float* __restrict__ bs,
             float* __restrict__ outp, int M) {
    __shared__ float As[32][132];   // [k][m], padded
    __shared__ float Bs[32][128];   // [k][n]

    const float* Bp; const float* bp; float* D; int ncols = 128;
    switch (blockIdx.y) {
        case 0: Bp = Wq; bp = bq; D = g_Q;  break;
        case 1: Bp = Wk; bp = bk; D = g_K;  break;
        case 2: Bp = Wv; bp = bv; D = g_V;  break;
        case 3: Bp = Ws; bp = bs; D = outp; break;
        default: Bp = g_Wqe; bp = g_bqW; D = g_QW; ncols = 64; break;
    }

    int m0 = blockIdx.x * 128;
    int t  = threadIdx.x;
    int tx = t & 15, ty = t >> 4;
    int ldb4 = ncols >> 2;

    u64 acc[8][4];
#pragma unroll
    for (int r = 0; r < 8; r++)
#pragma unroll
        for (int p = 0; p < 4; p++) acc[r][p] = 0ULL;

    for (int kk = 0; kk < 4; kk++) {
#pragma unroll
        for (int i = 0; i < 4; i++) {
            int row = (t >> 3) + i * 32;
            int c4  = t & 7;
            float4 v = make_float4(0.f, 0.f, 0.f, 0.f);
            if (m0 + row < M)
                v = ((const float4*)A)[(size_t)(m0 + row) * 32 + kk * 8 + c4];
            As[c4 * 4 + 0][row] = v.x;
            As[c4 * 4 + 1][row] = v.y;
            As[c4 * 4 + 2][row] = v.z;
            As[c4 * 4 + 3][row] = v.w;
        }
#pragma unroll
        for (int i = 0; i < 4; i++) {
            int idx = i * 256 + t;
            int r   = idx >> 5;
            int c4  = idx & 31;
            float4 v = make_float4(0.f, 0.f, 0.f, 0.f);
            if (c4 * 4 < ncols)
                v = ((const float4*)Bp)[(size_t)(kk * 32 + r) * ldb4 + c4];
            ((float4*)&Bs[r][0])[c4] = v;
        }
        __syncthreads();
#pragma unroll
        for (int k = 0; k < 32; k++) {
            float4 a0 = ((const float4*)&As[k][0])[ty];
            float4 a1 = ((const float4*)&As[k][0])[16 + ty];
            float4 b0 = ((const float4*)&Bs[k][0])[tx];
            float4 b1 = ((const float4*)&Bs[k][0])[16 + tx];
            u64 bpk[4] = { pack2(b0.x, b0.y), pack2(b0.z, b0.w),
                           pack2(b1.x, b1.y), pack2(b1.z, b1.w) };
            float av[8] = { a0.x, a0.y, a0.z, a0.w, a1.x, a1.y, a1.z, a1.w };
#pragma unroll
            for (int r = 0; r < 8; r++) {
                u64 ad = pack2(av[r], av[r]);
#pragma unroll
                for (int p = 0; p < 4; p++)
                    acc[r][p] = fma2(ad, bpk[p], acc[r][p]);
            }
        }
        __syncthreads();
    }

#pragma unroll
    for (int r = 0; r < 8; r++) {
        int mrow = (r < 4) ? (ty * 4 + r) : (64 + ty * 4 + r - 4);
        int m = m0 + mrow;
        if (m >= M) continue;
#pragma unroll
        for (int p = 0; p < 4; p++) {
            int c = (p < 2) ? (tx * 4 + p * 2) : (64 + tx * 4 + (p - 2) * 2);
            if (c >= ncols) continue;
            float lo, hi;
            unpack2(acc[r][p], lo, hi);
            float2 st = make_float2(lo + bp[c], hi + bp[c + 1]);
            *(float2*)&D[(size_t)m * ncols + c] = st;
        }
    }
}

// ---------------- counting sort: histogram, scan, scatter -------------------
__global__ void hist_kernel(const int* __restrict__ ei) {
    int i = blockIdx.x * 256 + threadIdx.x;
    if (i < N_EDGES) atomicAdd(&g_hist[ei[N_EDGES + i]], 1);
}

__device__ __forceinline__ int block_exscan(int v, int* sh) {
    int lane = threadIdx.x & 31, w = threadIdx.x >> 5;
    int incl = v;
#pragma unroll
    for (int s = 1; s < 32; s <<= 1) {
        int t = __shfl_up_sync(0xffffffffu, incl, s);
        if (lane >= s) incl += t;
    }
    if (lane == 31) sh[w] = incl;
    __syncthreads();
    if (threadIdx.x == 0) {
        int acc = 0;
#pragma unroll
        for (int i = 0; i < 8; i++) { int t = sh[i]; sh[i] = acc; acc += t; }
    }
    __syncthreads();
    return incl - v + sh[w];
}

__global__ void scan_a() {
    int i = blockIdx.x * 256 + threadIdx.x;
    int v = (i < N_NODES) ? g_hist[i] : 0;
#pragma unroll
    for (int s = 16; s >= 1; s >>= 1) v += __shfl_xor_sync(0xffffffffu, v, s);
    __shared__ int sh[8];
    if ((threadIdx.x & 31) == 0) sh[threadIdx.x >> 5] = v;
    __syncthreads();
    if (threadIdx.x == 0) {
        int s = 0;
#pragma unroll
        for (int j = 0; j < 8; j++) s += sh[j];
        g_bsum[blockIdx.x] = s;
    }
}

__global__ void scan_b(int nblk) {
    __shared__ int sh[8];
    int t = threadIdx.x;
    int v = (t < nblk) ? g_bsum[t] : 0;
    int ex = block_exscan(v, sh);
    if (t < nblk) g_bpre[t] = ex;
}

__global__ void scan_c() {
    __shared__ int sh[8];
    int i = blockIdx.x * 256 + threadIdx.x;
    int v = (i < N_NODES) ? g_hist[i] : 0;
    int ex = block_exscan(v, sh);
    if (i < N_NODES) {
        int off = g_bpre[blockIdx.x] + ex;
        g_off[i] = off;
        g_cursor[i] = off;
    }
}

__global__ void scatter_kernel(const int* __restrict__ ei) {
    int i = blockIdx.x * 256 + threadIdx.x;
    if (i < N_EDGES) {
        int dst = ei[N_EDGES + i];
        int pos = atomicAdd(&g_cursor[dst], 1);
        g_sorted2[pos] = make_int2(ei[i], i);
    }
}

// ---------------- fused per-node attention (warp per node) ------------------
__global__ __launch_bounds__(256)
void node_fused(const float* __restrict__ ea, const float* __restrict__ We,
                float* __restrict__ out) {
    __shared__ float We_s[32][128];   // 16KB
    __shared__ float eac_s[8][64];
    int t = threadIdx.x;
#pragma unroll
    for (int i = 0; i < 4; i++) {
        int idx = i * 256 + t;        // 1024 float4
        ((float4*)&We_s[0][0])[idx] = ((const float4*)We)[idx];
    }
    __syncthreads();

    int wrp = t >> 5, lane = t & 31;
    int n = blockIdx.x * 8 + wrp;     // 6250 * 8 = 50000 exact
    int half = lane >> 4, l15 = lane & 15;

    float4 q4  = ((const float4*)g_Q)[(size_t)n * 32 + lane];
    float2 qw2 = ((const float2*)g_QW)[(size_t)n * 32 + half * 16 + l15];
    int start = g_off[n];
    int end   = (n == N_NODES - 1) ? N_EDGES : g_off[n + 1];

    float4 vacc = make_float4(0.f, 0.f, 0.f, 0.f);
    float2 eacc = make_float2(0.f, 0.f);
    float denom = 0.f;

    for (int j = start; j < end; j++) {
        int2 se = g_sorted2[j];
        float4 k4 = ((const float4*)g_K)[(size_t)se.x * 32 + lane];
        float4 v4 = ((const float4*)g_V)[(size_t)se.x * 32 + lane];
        float2 e2 = ((const float2*)ea)[(size_t)se.y * 16 + l15];
        float part = q4.x * k4.x + q4.y * k4.y + q4.z * k4.z + q4.w * k4.w
                   + e2.x * qw2.x + e2.y * qw2.y;
        part += __shfl_xor_sync(0xffffffffu, part, 8);
        part += __shfl_xor_sync(0xffffffffu, part, 4);
        part += __shfl_xor_sync(0xffffffffu, part, 2);
        part += __shfl_xor_sync(0xffffffffu, part, 1);
        // per 16-lane half: head's logit sum; shift-free softmax (logits O(1))
        float alpha = __expf(part * 0.125f);
        denom += alpha;
        vacc.x += alpha * v4.x; vacc.y += alpha * v4.y;
        vacc.z += alpha * v4.z; vacc.w += alpha * v4.w;
        eacc.x += alpha * e2.x; eacc.y += alpha * e2.y;
    }

    float inv = 1.0f / (denom + 1e-16f);
    vacc.x *= inv; vacc.y *= inv; vacc.z *= inv; vacc.w *= inv;
    eacc.x *= inv; eacc.y *= inv;

    eac_s[wrp][half * 32 + 2 * l15]     = eacc.x;
    eac_s[wrp][half * 32 + 2 * l15 + 1] = eacc.y;
    __syncwarp();

    int cb = half * 64 + l15 * 4;
    float4 et = make_float4(0.f, 0.f, 0.f, 0.f);
#pragma unroll
    for (int d = 0; d < 32; d++) {
        float ed = eac_s[wrp][half * 32 + d];
        et.x += ed * We_s[d][cb + 0];
        et.y += ed * We_s[d][cb + 1];
        et.z += ed * We_s[d][cb + 2];
        et.w += ed * We_s[d][cb + 3];
    }

    float4 o = ((float4*)out)[(size_t)n * 32 + lane];   // holds skip projection
    o.x += vacc.x + et.x;
    o.y += vacc.y + et.y;
    o.z += vacc.z + et.z;
    o.w += vacc.w + et.w;
    ((float4*)out)[(size_t)n * 32 + lane] = o;
}

// ---------------- launcher ---------------------------------------------------
extern "C" void kernel_launch(void* const* d_in, const int* in_sizes, int n_in,
                              void* d_out, int out_size) {
    const float* x  = (const float*)d_in[0];
    const int*   ei = (const int*)d_in[1];
    const float* ea = (const float*)d_in[2];
    const float* Wq = (const float*)d_in[3];
    const float* bq = (const float*)d_in[4];
    const float* Wk = (const float*)d_in[5];
    const float* bk = (const float*)d_in[6];
    const float* Wv = (const float*)d_in[7];
    const float* bv = (const float*)d_in[8];
    const float* We = (const float*)d_in[9];
    const float* Ws = (const float*)d_in[10];
    const float* bs = (const float*)d_in[11];
    float* out = (float*)d_out;

    const int NB_NODE = (N_NODES + 255) / 256;   // 196
    const int NB_EDGE = (N_EDGES + 255) / 256;   // 3125

    zero_hist<<<NB_NODE, 256>>>();
    combine_we<<<33, 256>>>(Wq, bq, We);

    dim3 gg((N_NODES + 127) / 128, 5);
    gemm128<<<gg, 256>>>(x, Wq, bq, Wk, bk, Wv, bv, Ws, bs, out, N_NODES);

    hist_kernel<<<NB_EDGE, 256>>>(ei);
    scan_a<<<NB_NODE, 256>>>();
    scan_b<<<1, 256>>>(NB_NODE);
    scan_c<<<NB_NODE, 256>>>();
    scatter_kernel<<<NB_EDGE, 256>>>(ei);

    node_fused<<<N_NODES / 8, 256>>>(ea, We, out);
}